// round 8
// baseline (speedup 1.0000x reference)
#include <cuda_runtime.h>

#define S_LEN   2048
#define D_MODEL 4096
#define NH      32
#define NKV     8
#define HD      128

// Scratch (no allocations allowed): ~84 MB of __device__ globals.
static __device__ float g_xq[S_LEN * D_MODEL];       // [S, H*HD]  (RoPE'd Q)
static __device__ float g_xk[S_LEN * NKV * HD];      // [S, KVH*HD] (RoPE'd K)
static __device__ float g_xv[S_LEN * NKV * HD];      // [S, KVH*HD]
static __device__ float g_xo[S_LEN * D_MODEL];       // attention output [S, H*HD]

// ---------------------------------------------------------------------------
// Tiled fp32 GEMM: C[M,N] = A[M,K] @ B[K,N], row-major, all dims multiples of
// the tile. 128x128 block tile, K-step 8, 256 threads, 8x8 per-thread microtile.
// Optional fused RoPE epilogue (per-head rotation on 128-wide head dims).
// ---------------------------------------------------------------------------
template <bool ROPE>
__global__ void __launch_bounds__(256) gemm_k(
    const float* __restrict__ A, const float* __restrict__ B, float* __restrict__ C,
    int M, int N, int K,
    const float* __restrict__ fc, const float* __restrict__ fs)
{
    __shared__ float As[8][132];   // padded stride: conflict-free transpose store
    __shared__ float Bs[8][132];

    const int tid  = threadIdx.x;
    const int tx   = tid & 15;         // 16 col-groups of 8
    const int ty   = tid >> 4;         // 16 row-groups of 8
    const int row0 = blockIdx.y * 128;
    const int n0   = blockIdx.x * 128;

    const int a_row = tid >> 1;
    const int a_c4  = (tid & 1) << 2;
    const int b_row = tid >> 5;
    const int b_c4  = (tid & 31) << 2;

    const float* Ap = A + (size_t)(row0 + a_row) * K + a_c4;
    const float* Bp = B + (size_t)b_row * N + n0 + b_c4;

    float acc[8][8];
    #pragma unroll
    for (int i = 0; i < 8; i++)
        #pragma unroll
        for (int j = 0; j < 8; j++) acc[i][j] = 0.f;

    for (int k0 = 0; k0 < K; k0 += 8) {
        const float4 av = *(const float4*)(Ap + k0);
        const float4 bv = *(const float4*)(Bp + (size_t)k0 * N);
        __syncthreads();
        As[a_c4 + 0][a_row] = av.x;
        As[a_c4 + 1][a_row] = av.y;
        As[a_c4 + 2][a_row] = av.z;
        As[a_c4 + 3][a_row] = av.w;
        *(float4*)&Bs[b_row][b_c4] = bv;
        __syncthreads();

        #pragma unroll
        for (int kk = 0; kk < 8; kk++) {
            float a[8], b[8];
            *(float4*)(a)     = *(const float4*)&As[kk][ty * 8];
            *(float4*)(a + 4) = *(const float4*)&As[kk][ty * 8 + 4];
            *(float4*)(b)     = *(const float4*)&Bs[kk][tx * 8];
            *(float4*)(b + 4) = *(const float4*)&Bs[kk][tx * 8 + 4];
            #pragma unroll
            for (int i = 0; i < 8; i++)
                #pragma unroll
                for (int j = 0; j < 8; j++)
                    acc[i][j] = fmaf(a[i], b[j], acc[i][j]);
        }
    }

    #pragma unroll
    for (int i = 0; i < 8; i++) {
        const int srow = row0 + ty * 8 + i;
        float v[8];
        if (ROPE) {
            const int colbase = n0 + tx * 8;
            #pragma unroll
            for (int j = 0; j < 8; j += 2) {
                const int pi   = ((colbase + j) & (HD - 1)) >> 1;
                const float c  = fc[srow * (HD / 2) + pi];
                const float sn = fs[srow * (HD / 2) + pi];
                const float t0 = acc[i][j], t1 = acc[i][j + 1];
                v[j]     = t0 * c  - t1 * sn;
                v[j + 1] = t0 * sn + t1 * c;
            }
        } else {
            #pragma unroll
            for (int j = 0; j < 8; j++) v[j] = acc[i][j];
        }
        float4* dst = (float4*)&C[(size_t)srow * N + n0 + tx * 8];
        dst[0] = *(float4*)(v);
        dst[1] = *(float4*)(v + 4);
    }
}

// ---------------------------------------------------------------------------
// Flash attention (fp32, online softmax). One CTA = (head h, 64 Q rows).
// GQA: kv head = h / 4. Causal: only qt+1 K-tiles processed.
// 256 threads: score phase 16x16 grid of 4x4 microtiles over S[64,64];
// PV phase 16x16 grid of 4x8 microtiles over O[64,128].
// ---------------------------------------------------------------------------
__global__ void __launch_bounds__(256) attn_k(
    const float* __restrict__ xq, const float* __restrict__ xk,
    const float* __restrict__ xv, float* __restrict__ xo)
{
    extern __shared__ float sm[];
    float* Qs   = sm;                  // 64 x 132
    float* Ks   = Qs + 64 * 132;       // 64 x 132
    float* Vs   = Ks + 64 * 132;       // 64 x 132
    float* Ps   = Vs + 64 * 132;       // 64 x 65
    float* mS   = Ps + 64 * 65;        // 64
    float* lS   = mS + 64;             // 64
    float* facS = lS + 64;             // 64

    const int tid = threadIdx.x;
    const int qt  = (int)gridDim.x - 1 - (int)blockIdx.x;  // heavy tiles first
    const int h   = blockIdx.y;
    const int hk  = h >> 2;            // H / KVH = 4
    const int q0  = qt * 64;
    const int sr  = tid >> 4;          // row group (4 rows)
    const int sc  = tid & 15;          // col group
    const float scale = 0.08838834764831845f;  // 1/sqrt(128)

    // Load Q tile [64,128] (coalesced float4)
    #pragma unroll
    for (int i = 0; i < 8; i++) {
        const int e = tid + i * 256;
        const int r = e >> 5, d4 = (e & 31) << 2;
        *(float4*)&Qs[r * 132 + d4] =
            *(const float4*)&xq[(size_t)(q0 + r) * D_MODEL + h * HD + d4];
    }
    if (tid < 64) { mS[tid] = -3.0e38f; lS[tid] = 0.f; }

    float accO[4][8];
    #pragma unroll
    for (int r = 0; r < 4; r++)
        #pragma unroll
        for (int j = 0; j < 8; j++) accO[r][j] = 0.f;

    for (int kt = 0; kt <= qt; kt++) {
        const int k0 = kt * 64;
        __syncthreads();  // prev PV done with Ks/Vs/Ps; m/l stable

        float m_old[4], l_old[4];
        #pragma unroll
        for (int r = 0; r < 4; r++) {
            m_old[r] = mS[sr * 4 + r];
            l_old[r] = lS[sr * 4 + r];
        }

        // Load K,V tiles [64,128]
        #pragma unroll
        for (int i = 0; i < 8; i++) {
            const int e = tid + i * 256;
            const int r = e >> 5, d4 = (e & 31) << 2;
            const size_t off = (size_t)(k0 + r) * (NKV * HD) + hk * HD + d4;
            *(float4*)&Ks[r * 132 + d4] = *(const float4*)&xk[off];
            *(float4*)&Vs[r * 132 + d4] = *(const float4*)&xv[off];
        }
        __syncthreads();

        // Scores s[4][4] = Q[sr*4+r] . K[sc*4+c]
        float s[4][4];
        #pragma unroll
        for (int r = 0; r < 4; r++)
            #pragma unroll
            for (int c = 0; c < 4; c++) s[r][c] = 0.f;

        #pragma unroll 4
        for (int d4 = 0; d4 < 32; d4++) {
            float4 a[4], b[4];
            #pragma unroll
            for (int r = 0; r < 4; r++)
                a[r] = *(const float4*)&Qs[(sr * 4 + r) * 132 + d4 * 4];
            #pragma unroll
            for (int c = 0; c < 4; c++)
                b[c] = *(const float4*)&Ks[(sc * 4 + c) * 132 + d4 * 4];
            #pragma unroll
            for (int r = 0; r < 4; r++)
                #pragma unroll
                for (int c = 0; c < 4; c++)
                    s[r][c] += a[r].x * b[c].x + a[r].y * b[c].y +
                               a[r].z * b[c].z + a[r].w * b[c].w;
        }

        const bool diag = (kt == qt);
        #pragma unroll
        for (int r = 0; r < 4; r++)
            #pragma unroll
            for (int c = 0; c < 4; c++) {
                float val = s[r][c] * scale;
                if (diag && (sc * 4 + c) > (sr * 4 + r)) val = -1e30f;
                s[r][c] = val;
            }

        // Online softmax per row (16 threads per row via half-warp shfl)
        #pragma unroll
        for (int r = 0; r < 4; r++) {
            float tm = fmaxf(fmaxf(s[r][0], s[r][1]), fmaxf(s[r][2], s[r][3]));
            #pragma unroll
            for (int o = 8; o; o >>= 1)
                tm = fmaxf(tm, __shfl_xor_sync(0xffffffffu, tm, o));
            const float m_new = fmaxf(m_old[r], tm);

            float rs = 0.f;
            #pragma unroll
            for (int c = 0; c < 4; c++) {
                const float p = __expf(s[r][c] - m_new);
                s[r][c] = p;
                rs += p;
            }
            #pragma unroll
            for (int o = 8; o; o >>= 1)
                rs += __shfl_xor_sync(0xffffffffu, rs, o);

            if (sc == 0) {
                const float f = __expf(m_old[r] - m_new);
                facS[sr * 4 + r] = f;
                lS[sr * 4 + r]   = l_old[r] * f + rs;
                mS[sr * 4 + r]   = m_new;
            }
            #pragma unroll
            for (int c = 0; c < 4; c++)
                Ps[(sr * 4 + r) * 65 + sc * 4 + c] = s[r][c];
        }
        __syncthreads();

        // Rescale accumulator, then O += P @ V
        #pragma unroll
        for (int r = 0; r < 4; r++) {
            const float f = facS[sr * 4 + r];
            #pragma unroll
            for (int j = 0; j < 8; j++) accO[r][j] *= f;
        }
        #pragma unroll 4
        for (int c = 0; c < 64; c++) {
            const float4 v0 = *(const float4*)&Vs[c * 132 + sc * 8];
            const float4 v1 = *(const float4*)&Vs[c * 132 + sc * 8 + 4];
            #pragma unroll
            for (int r = 0; r < 4; r++) {
                const float p = Ps[(sr * 4 + r) * 65 + c];
                accO[r][0] = fmaf(p, v0.x, accO[r][0]);
                accO[r][1] = fmaf(p, v0.y, accO[r][1]);
                accO[r][2] = fmaf(p, v0.z, accO[r][2]);
                accO[r][3] = fmaf(p, v0.w, accO[r][3]);
                accO[r][4] = fmaf(p, v1.x, accO[r][4]);
                accO[r][5] = fmaf(p, v1.y, accO[r][5]);
                accO[r][6] = fmaf(p, v1.z, accO[r][6]);
                accO[r][7] = fmaf(p, v1.w, accO[r][7]);
            }
        }
    }

    // Normalize and write out: xo[q, h*HD + d]
    #pragma unroll
    for (int r = 0; r < 4; r++) {
        const float inv = 1.f / lS[sr * 4 + r];
        float v[8];
        #pragma unroll
        for (int j = 0; j < 8; j++) v[j] = accO[r][j] * inv;
        float4* dst = (float4*)&xo[(size_t)(q0 + sr * 4 + r) * D_MODEL + h * HD + sc * 8];
        dst[0] = *(float4*)(v);
        dst[1] = *(float4*)(v + 4);
    }
}

// ---------------------------------------------------------------------------
// Launch: 5 kernels on the default stream. Graph-capturable, allocation-free.
// ---------------------------------------------------------------------------
extern "C" void kernel_launch(void* const* d_in, const int* in_sizes, int n_in,
                              void* d_out, int out_size)
{
    const float* x  = (const float*)d_in[0];
    const float* wq = (const float*)d_in[1];
    const float* wk = (const float*)d_in[2];
    const float* wv = (const float*)d_in[3];
    const float* wo = (const float*)d_in[4];
    const float* fc = (const float*)d_in[5];
    const float* fs = (const float*)d_in[6];
    float* out = (float*)d_out;

    float *xq, *xk, *xv, *xo;
    cudaGetSymbolAddress((void**)&xq, g_xq);
    cudaGetSymbolAddress((void**)&xk, g_xk);
    cudaGetSymbolAddress((void**)&xv, g_xv);
    cudaGetSymbolAddress((void**)&xo, g_xo);

    const int smem_attn = (3 * 64 * 132 + 64 * 65 + 3 * 64) * (int)sizeof(float);
    cudaFuncSetAttribute(attn_k, cudaFuncAttributeMaxDynamicSharedMemorySize, smem_attn);

    dim3 blk(256);
    // Q = x @ wq (+RoPE)
    gemm_k<true ><<<dim3(D_MODEL / 128, S_LEN / 128), blk>>>(
        x, wq, xq, S_LEN, D_MODEL, D_MODEL, fc, fs);
    // K = x @ wk (+RoPE)
    gemm_k<true ><<<dim3((NKV * HD) / 128, S_LEN / 128), blk>>>(
        x, wk, xk, S_LEN, NKV * HD, D_MODEL, fc, fs);
    // V = x @ wv
    gemm_k<false><<<dim3((NKV * HD) / 128, S_LEN / 128), blk>>>(
        x, wv, xv, S_LEN, NKV * HD, D_MODEL, nullptr, nullptr);
    // Attention
    attn_k<<<dim3(S_LEN / 64, NH), blk, smem_attn>>>(xq, xk, xv, xo);
    // out = xo @ wo
    gemm_k<false><<<dim3(D_MODEL / 128, S_LEN / 128), blk>>>(
        xo, wo, out, S_LEN, D_MODEL, D_MODEL, nullptr, nullptr);
}

// round 10
// speedup vs baseline: 1.9242x; 1.9242x over previous
#include <cuda_runtime.h>
#include <cuda_bf16.h>
#include <cstdint>
#include <cstddef>

#define S_LEN   2048
#define D_MODEL 4096
#define NH      32
#define NKV     8
#define HD      128
#define KVD     (NKV * HD)   // 1024

// ---------------------------------------------------------------------------
// Scratch (__device__ globals; no allocations allowed anywhere).
// ---------------------------------------------------------------------------
static __device__ float g_xq[S_LEN * D_MODEL];
static __device__ float g_xk[S_LEN * KVD];
static __device__ float g_xv[S_LEN * KVD];
static __device__ float g_xo[S_LEN * D_MODEL];

static __device__ __nv_bfloat16 g_xhi[S_LEN * D_MODEL],  g_xlo[S_LEN * D_MODEL];
static __device__ __nv_bfloat16 g_wqhi[D_MODEL * D_MODEL], g_wqlo[D_MODEL * D_MODEL];
static __device__ __nv_bfloat16 g_wkhi[D_MODEL * KVD],   g_wklo[D_MODEL * KVD];
static __device__ __nv_bfloat16 g_wvhi[D_MODEL * KVD],   g_wvlo[D_MODEL * KVD];
static __device__ __nv_bfloat16 g_wohi[D_MODEL * D_MODEL], g_wolo[D_MODEL * D_MODEL];
static __device__ __nv_bfloat16 g_xohi[S_LEN * D_MODEL], g_xolo[S_LEN * D_MODEL];

// ---------------------------------------------------------------------------
// Helpers: smem address, cp.async, ldmatrix, mma
// ---------------------------------------------------------------------------
__device__ __forceinline__ uint32_t s2u(const void* p) {
    return (uint32_t)__cvta_generic_to_shared(p);
}
__device__ __forceinline__ void cpa(uint32_t s, const void* g) {
    asm volatile("cp.async.cg.shared.global [%0], [%1], 16;\n" :: "r"(s), "l"(g));
}
__device__ __forceinline__ void ldsm4(uint32_t r[4], uint32_t a) {
    asm volatile("ldmatrix.sync.aligned.m8n8.x4.shared.b16 {%0,%1,%2,%3}, [%4];"
                 : "=r"(r[0]), "=r"(r[1]), "=r"(r[2]), "=r"(r[3]) : "r"(a));
}
__device__ __forceinline__ void ldsm4t(uint32_t r[4], uint32_t a) {
    asm volatile("ldmatrix.sync.aligned.m8n8.x4.trans.shared.b16 {%0,%1,%2,%3}, [%4];"
                 : "=r"(r[0]), "=r"(r[1]), "=r"(r[2]), "=r"(r[3]) : "r"(a));
}
__device__ __forceinline__ void mma16816(float c[4], const uint32_t a[4], const uint32_t b[2]) {
    asm volatile(
        "mma.sync.aligned.m16n8k16.row.col.f32.bf16.bf16.f32 "
        "{%0,%1,%2,%3}, {%4,%5,%6,%7}, {%8,%9}, {%0,%1,%2,%3};"
        : "+f"(c[0]), "+f"(c[1]), "+f"(c[2]), "+f"(c[3])
        : "r"(a[0]), "r"(a[1]), "r"(a[2]), "r"(a[3]), "r"(b[0]), "r"(b[1]));
}

// ---------------------------------------------------------------------------
// Split fp32 -> (bf16 hi, bf16 lo). Exact residual: lo = bf16(x - float(hi)).
// n4 = element count / 4.
// ---------------------------------------------------------------------------
__global__ void split_k(const float* __restrict__ in, __nv_bfloat16* __restrict__ hi,
                        __nv_bfloat16* __restrict__ lo, int n4)
{
    const int i = blockIdx.x * 256 + threadIdx.x;
    if (i >= n4) return;
    const float4 v = ((const float4*)in)[i];
    const float x[4] = {v.x, v.y, v.z, v.w};
    union { __nv_bfloat16 h[4]; uint2 u; } H, L;
    #pragma unroll
    for (int k = 0; k < 4; ++k) {
        H.h[k] = __float2bfloat16(x[k]);
        L.h[k] = __float2bfloat16(x[k] - __bfloat162float(H.h[k]));
    }
    ((uint2*)hi)[i] = H.u;
    ((uint2*)lo)[i] = L.u;
}

// ---------------------------------------------------------------------------
// Tensor-core GEMM with 2-term bf16 split: C = Ah*Bh + Ah*Bl + Al*Bh (fp32 acc).
// 128x128x32 CTA tile, 256 threads (8 warps, 4m x 2n), mma.sync m16n8k16.
// cp.async double-buffered. Optional fused RoPE epilogue (128-wide heads).
// Smem pitches: A 40 halves, B 136 halves -> conflict-free ldmatrix.
// ---------------------------------------------------------------------------
#define GEMM_SMEM ((2*128*40*2 + 2*32*136*2) * 2)   // 75776 bytes

template <bool ROPE>
__global__ void __launch_bounds__(256) gemm_mma(
    const __nv_bfloat16* __restrict__ Ah, const __nv_bfloat16* __restrict__ Al,
    const __nv_bfloat16* __restrict__ Bh, const __nv_bfloat16* __restrict__ Bl,
    float* __restrict__ C, int M, int N, int K,
    const float* __restrict__ fc, const float* __restrict__ fs)
{
    extern __shared__ __nv_bfloat16 smem[];
    __nv_bfloat16* As_h = smem;                    // [2][128][40]
    __nv_bfloat16* As_l = As_h + 2 * 128 * 40;
    __nv_bfloat16* Bs_h = As_l + 2 * 128 * 40;     // [2][32][136]
    __nv_bfloat16* Bs_l = Bs_h + 2 * 32 * 136;

    const int tid  = threadIdx.x;
    const int lane = tid & 31;
    const int wid  = tid >> 5;
    const int wm   = wid & 3;          // 4 warps along M
    const int wn   = wid >> 2;         // 2 warps along N
    const int row0 = blockIdx.y * 128;
    const int n0   = blockIdx.x * 128;

    auto prefetch = [&](int t, int buf) {
        const int k0 = t * 32;
        #pragma unroll
        for (int p = 0; p < 2; ++p) {
            const int e = tid + p * 256;
            const int r = e >> 2, c = (e & 3) * 8;
            const size_t g = (size_t)(row0 + r) * K + k0 + c;
            const int so = (buf * 128 + r) * 40 + c;
            cpa(s2u(As_h + so), Ah + g);
            cpa(s2u(As_l + so), Al + g);
        }
        #pragma unroll
        for (int p = 0; p < 2; ++p) {
            const int e = tid + p * 256;
            const int r = e >> 4, c = (e & 15) * 8;
            const size_t g = (size_t)(k0 + r) * N + n0 + c;
            const int so = (buf * 32 + r) * 136 + c;
            cpa(s2u(Bs_h + so), Bh + g);
            cpa(s2u(Bs_l + so), Bl + g);
        }
        asm volatile("cp.async.commit_group;\n");
    };

    float acc[2][8][4];
    #pragma unroll
    for (int i = 0; i < 2; ++i)
        #pragma unroll
        for (int j = 0; j < 8; ++j)
            #pragma unroll
            for (int q = 0; q < 4; ++q) acc[i][j][q] = 0.f;

    const int T = K / 32;
    prefetch(0, 0);

    for (int t = 0; t < T; ++t) {
        asm volatile("cp.async.wait_group 0;\n");
        __syncthreads();
        if (t + 1 < T) prefetch(t + 1, (t + 1) & 1);

        const int buf = t & 1;
        const __nv_bfloat16* Abh = As_h + buf * 128 * 40;
        const __nv_bfloat16* Abl = As_l + buf * 128 * 40;
        const __nv_bfloat16* Bbh = Bs_h + buf * 32 * 136;
        const __nv_bfloat16* Bbl = Bs_l + buf * 32 * 136;

        #pragma unroll
        for (int kk = 0; kk < 2; ++kk) {
            uint32_t ah[2][4], al[2][4];
            #pragma unroll
            for (int i = 0; i < 2; ++i) {
                const int rr = wm * 32 + i * 16 + (lane & 15);
                const int cc = kk * 16 + ((lane >> 4) << 3);
                ldsm4(ah[i], s2u(Abh + rr * 40 + cc));
                ldsm4(al[i], s2u(Abl + rr * 40 + cc));
            }
            uint32_t bh[8][2], bl[8][2];
            #pragma unroll
            for (int jj = 0; jj < 4; ++jj) {
                const int rr = kk * 16 + (lane & 15);
                const int cc = wn * 64 + jj * 16 + ((lane >> 4) << 3);
                uint32_t r4[4];
                ldsm4t(r4, s2u(Bbh + rr * 136 + cc));
                bh[2*jj][0] = r4[0]; bh[2*jj][1] = r4[1];
                bh[2*jj+1][0] = r4[2]; bh[2*jj+1][1] = r4[3];
                ldsm4t(r4, s2u(Bbl + rr * 136 + cc));
                bl[2*jj][0] = r4[0]; bl[2*jj][1] = r4[1];
                bl[2*jj+1][0] = r4[2]; bl[2*jj+1][1] = r4[3];
            }
            #pragma unroll
            for (int i = 0; i < 2; ++i)
                #pragma unroll
                for (int j = 0; j < 8; ++j) {
                    mma16816(acc[i][j], ah[i], bh[j]);
                    mma16816(acc[i][j], ah[i], bl[j]);
                    mma16816(acc[i][j], al[i], bh[j]);
                }
        }
        __syncthreads();
    }

    // Epilogue: (c0,c1) = row rbase cols (col,col+1); (c2,c3) = row rbase+8.
    const int g  = lane >> 2;
    const int tq = lane & 3;
    #pragma unroll
    for (int i = 0; i < 2; ++i) {
        const int rbase = row0 + wm * 32 + i * 16 + g;
        #pragma unroll
        for (int j = 0; j < 8; ++j) {
            const int col = n0 + wn * 64 + j * 8 + tq * 2;
            float v0 = acc[i][j][0], v1 = acc[i][j][1];
            float v2 = acc[i][j][2], v3 = acc[i][j][3];
            if (ROPE) {
                const int pi = (col & (HD - 1)) >> 1;
                const float c0 = fc[rbase * (HD/2) + pi];
                const float s0 = fs[rbase * (HD/2) + pi];
                const float c1 = fc[(rbase + 8) * (HD/2) + pi];
                const float s1 = fs[(rbase + 8) * (HD/2) + pi];
                float t0 = v0, t1 = v1;
                v0 = t0 * c0 - t1 * s0;  v1 = t0 * s0 + t1 * c0;
                t0 = v2; t1 = v3;
                v2 = t0 * c1 - t1 * s1;  v3 = t0 * s1 + t1 * c1;
            }
            *(float2*)&C[(size_t)rbase * N + col]       = make_float2(v0, v1);
            *(float2*)&C[(size_t)(rbase + 8) * N + col] = make_float2(v2, v3);
        }
    }
}

// ---------------------------------------------------------------------------
// Flash attention (fp32, online softmax) — proven R8 version, unchanged.
// ---------------------------------------------------------------------------
__global__ void __launch_bounds__(256) attn_k(
    const float* __restrict__ xq, const float* __restrict__ xk,
    const float* __restrict__ xv, float* __restrict__ xo)
{
    extern __shared__ float sm[];
    float* Qs   = sm;
    float* Ks   = Qs + 64 * 132;
    float* Vs   = Ks + 64 * 132;
    float* Ps   = Vs + 64 * 132;
    float* mS   = Ps + 64 * 65;
    float* lS   = mS + 64;
    float* facS = lS + 64;

    const int tid = threadIdx.x;
    const int qt  = (int)gridDim.x - 1 - (int)blockIdx.x;
    const int h   = blockIdx.y;
    const int hk  = h >> 2;
    const int q0  = qt * 64;
    const int sr  = tid >> 4;
    const int sc  = tid & 15;
    const float scale = 0.08838834764831845f;

    #pragma unroll
    for (int i = 0; i < 8; i++) {
        const int e = tid + i * 256;
        const int r = e >> 5, d4 = (e & 31) << 2;
        *(float4*)&Qs[r * 132 + d4] =
            *(const float4*)&xq[(size_t)(q0 + r) * D_MODEL + h * HD + d4];
    }
    if (tid < 64) { mS[tid] = -3.0e38f; lS[tid] = 0.f; }

    float accO[4][8];
    #pragma unroll
    for (int r = 0; r < 4; r++)
        #pragma unroll
        for (int j = 0; j < 8; j++) accO[r][j] = 0.f;

    for (int kt = 0; kt <= qt; kt++) {
        const int k0 = kt * 64;
        __syncthreads();

        float m_old[4], l_old[4];
        #pragma unroll
        for (int r = 0; r < 4; r++) {
            m_old[r] = mS[sr * 4 + r];
            l_old[r] = lS[sr * 4 + r];
        }

        #pragma unroll
        for (int i = 0; i < 8; i++) {
            const int e = tid + i * 256;
            const int r = e >> 5, d4 = (e & 31) << 2;
            const size_t off = (size_t)(k0 + r) * KVD + hk * HD + d4;
            *(float4*)&Ks[r * 132 + d4] = *(const float4*)&xk[off];
            *(float4*)&Vs[r * 132 + d4] = *(const float4*)&xv[off];
        }
        __syncthreads();

        float s[4][4];
        #pragma unroll
        for (int r = 0; r < 4; r++)
            #pragma unroll
            for (int c = 0; c < 4; c++) s[r][c] = 0.f;

        #pragma unroll 4
        for (int d4 = 0; d4 < 32; d4++) {
            float4 a[4], b[4];
            #pragma unroll
            for (int r = 0; r < 4; r++)
                a[r] = *(const float4*)&Qs[(sr * 4 + r) * 132 + d4 * 4];
            #pragma unroll
            for (int c = 0; c < 4; c++)
                b[c] = *(const float4*)&Ks[(sc * 4 + c) * 132 + d4 * 4];
            #pragma unroll
            for (int r = 0; r < 4; r++)
                #pragma unroll
                for (int c = 0; c < 4; c++)
                    s[r][c] += a[r].x * b[c].x + a[r].y * b[c].y +
                               a[r].z * b[c].z + a[r].w * b[c].w;
        }

        const bool diag = (kt == qt);
        #pragma unroll
        for (int r = 0; r < 4; r++)
            #pragma unroll
            for (int c = 0; c < 4; c++) {
                float val = s[r][c] * scale;
                if (diag && (sc * 4 + c) > (sr * 4 + r)) val = -1e30f;
                s[r][c] = val;
            }

        #pragma unroll
        for (int r = 0; r < 4; r++) {
            float tm = fmaxf(fmaxf(s[r][0], s[r][1]), fmaxf(s[r][2], s[r][3]));
            #pragma unroll
            for (int o = 8; o; o >>= 1)
                tm = fmaxf(tm, __shfl_xor_sync(0xffffffffu, tm, o));
            const float m_new = fmaxf(m_old[r], tm);

            float rs = 0.f;
            #pragma unroll
            for (int c = 0; c < 4; c++) {
                const float p = __expf(s[r][c] - m_new);
                s[r][c] = p;
                rs += p;
            }
            #pragma unroll
            for (int o = 8; o; o >>= 1)
                rs += __shfl_xor_sync(0xffffffffu, rs, o);

            if (sc == 0) {
                const float f = __expf(m_old[r] - m_new);
                facS[sr * 4 + r] = f;
                lS[sr * 4 + r]   = l_old[r] * f + rs;
                mS[sr * 4 + r]   = m_new;
            }
            #pragma unroll
            for (int c = 0; c < 4; c++)
                Ps[(sr * 4 + r) * 65 + sc * 4 + c] = s[r][c];
        }
        __syncthreads();

        #pragma unroll
        for (int r = 0; r < 4; r++) {
            const float f = facS[sr * 4 + r];
            #pragma unroll
            for (int j = 0; j < 8; j++) accO[r][j] *= f;
        }
        #pragma unroll 4
        for (int c = 0; c < 64; c++) {
            const float4 v0 = *(const float4*)&Vs[c * 132 + sc * 8];
            const float4 v1 = *(const float4*)&Vs[c * 132 + sc * 8 + 4];
            #pragma unroll
            for (int r = 0; r < 4; r++) {
                const float p = Ps[(sr * 4 + r) * 65 + c];
                accO[r][0] = fmaf(p, v0.x, accO[r][0]);
                accO[r][1] = fmaf(p, v0.y, accO[r][1]);
                accO[r][2] = fmaf(p, v0.z, accO[r][2]);
                accO[r][3] = fmaf(p, v0.w, accO[r][3]);
                accO[r][4] = fmaf(p, v1.x, accO[r][4]);
                accO[r][5] = fmaf(p, v1.y, accO[r][5]);
                accO[r][6] = fmaf(p, v1.z, accO[r][6]);
                accO[r][7] = fmaf(p, v1.w, accO[r][7]);
            }
        }
    }

    #pragma unroll
    for (int r = 0; r < 4; r++) {
        const float inv = 1.f / lS[sr * 4 + r];
        float v[8];
        #pragma unroll
        for (int j = 0; j < 8; j++) v[j] = accO[r][j] * inv;
        float4* dst = (float4*)&xo[(size_t)(q0 + sr * 4 + r) * D_MODEL + h * HD + sc * 8];
        dst[0] = *(float4*)(v);
        dst[1] = *(float4*)(v + 4);
    }
}

// ---------------------------------------------------------------------------
// Launch: split conversions + 4 tensor-core GEMMs + attention. Graph-capturable.
// ---------------------------------------------------------------------------
extern "C" void kernel_launch(void* const* d_in, const int* in_sizes, int n_in,
                              void* d_out, int out_size)
{
    const float* x  = (const float*)d_in[0];
    const float* wq = (const float*)d_in[1];
    const float* wk = (const float*)d_in[2];
    const float* wv = (const float*)d_in[3];
    const float* wo = (const float*)d_in[4];
    const float* fc = (const float*)d_in[5];
    const float* fs = (const float*)d_in[6];
    float* out = (float*)d_out;

    float *xq, *xk, *xv, *xo;
    __nv_bfloat16 *xhi, *xlo, *wqhi, *wqlo, *wkhi, *wklo, *wvhi, *wvlo,
                  *wohi, *wolo, *xohi, *xolo;
    cudaGetSymbolAddress((void**)&xq, g_xq);
    cudaGetSymbolAddress((void**)&xk, g_xk);
    cudaGetSymbolAddress((void**)&xv, g_xv);
    cudaGetSymbolAddress((void**)&xo, g_xo);
    cudaGetSymbolAddress((void**)&xhi, g_xhi);   cudaGetSymbolAddress((void**)&xlo, g_xlo);
    cudaGetSymbolAddress((void**)&wqhi, g_wqhi); cudaGetSymbolAddress((void**)&wqlo, g_wqlo);
    cudaGetSymbolAddress((void**)&wkhi, g_wkhi); cudaGetSymbolAddress((void**)&wklo, g_wklo);
    cudaGetSymbolAddress((void**)&wvhi, g_wvhi); cudaGetSymbolAddress((void**)&wvlo, g_wvlo);
    cudaGetSymbolAddress((void**)&wohi, g_wohi); cudaGetSymbolAddress((void**)&wolo, g_wolo);
    cudaGetSymbolAddress((void**)&xohi, g_xohi); cudaGetSymbolAddress((void**)&xolo, g_xolo);

    const int smem_attn = (3 * 64 * 132 + 64 * 65 + 3 * 64) * (int)sizeof(float);
    cudaFuncSetAttribute(attn_k, cudaFuncAttributeMaxDynamicSharedMemorySize, smem_attn);
    cudaFuncSetAttribute(gemm_mma<true >, cudaFuncAttributeMaxDynamicSharedMemorySize, GEMM_SMEM);
    cudaFuncSetAttribute(gemm_mma<false>, cudaFuncAttributeMaxDynamicSharedMemorySize, GEMM_SMEM);

    // Split conversions
    {
        int n4 = S_LEN * D_MODEL / 4;
        split_k<<<(n4 + 255) / 256, 256>>>(x, xhi, xlo, n4);
        n4 = D_MODEL * D_MODEL / 4;
        split_k<<<(n4 + 255) / 256, 256>>>(wq, wqhi, wqlo, n4);
        split_k<<<(n4 + 255) / 256, 256>>>(wo, wohi, wolo, n4);
        n4 = D_MODEL * KVD / 4;
        split_k<<<(n4 + 255) / 256, 256>>>(wk, wkhi, wklo, n4);
        split_k<<<(n4 + 255) / 256, 256>>>(wv, wvhi, wvlo, n4);
    }

    dim3 blk(256);
    // Q = x @ wq (+RoPE)
    gemm_mma<true ><<<dim3(D_MODEL / 128, S_LEN / 128), blk, GEMM_SMEM>>>(
        xhi, xlo, wqhi, wqlo, xq, S_LEN, D_MODEL, D_MODEL, fc, fs);
    // K = x @ wk (+RoPE)
    gemm_mma<true ><<<dim3(KVD / 128, S_LEN / 128), blk, GEMM_SMEM>>>(
        xhi, xlo, wkhi, wklo, xk, S_LEN, KVD, D_MODEL, fc, fs);
    // V = x @ wv
    gemm_mma<false><<<dim3(KVD / 128, S_LEN / 128), blk, GEMM_SMEM>>>(
        xhi, xlo, wvhi, wvlo, xv, S_LEN, KVD, D_MODEL, nullptr, nullptr);
    // Attention
    attn_k<<<dim3(S_LEN / 64, NH), blk, smem_attn>>>(xq, xk, xv, xo);
    // out = xo @ wo
    {
        int n4 = S_LEN * D_MODEL / 4;
        split_k<<<(n4 + 255) / 256, 256>>>(xo, xohi, xolo, n4);
    }
    gemm_mma<false><<<dim3(D_MODEL / 128, S_LEN / 128), blk, GEMM_SMEM>>>(
        xohi, xolo, wohi, wolo, out, S_LEN, D_MODEL, D_MODEL, nullptr, nullptr);
}

// round 13
// speedup vs baseline: 3.5651x; 1.8528x over previous
#include <cuda_runtime.h>
#include <cuda_bf16.h>
#include <cstdint>
#include <cstddef>

#define S_LEN   2048
#define D_MODEL 4096
#define NH      32
#define NKV     8
#define HD      128
#define KVD     (NKV * HD)   // 1024

// ---------------------------------------------------------------------------
// Scratch (__device__ globals; no allocations allowed anywhere).
// ---------------------------------------------------------------------------
static __device__ __nv_bfloat16 g_xhi[S_LEN * D_MODEL],  g_xlo[S_LEN * D_MODEL];
static __device__ __nv_bfloat16 g_wqhi[D_MODEL * D_MODEL], g_wqlo[D_MODEL * D_MODEL];
static __device__ __nv_bfloat16 g_wkhi[D_MODEL * KVD],   g_wklo[D_MODEL * KVD];
static __device__ __nv_bfloat16 g_wvhi[D_MODEL * KVD],   g_wvlo[D_MODEL * KVD];
static __device__ __nv_bfloat16 g_wohi[D_MODEL * D_MODEL], g_wolo[D_MODEL * D_MODEL];

static __device__ __nv_bfloat16 g_qhi[S_LEN * D_MODEL], g_qlo[S_LEN * D_MODEL];
static __device__ __nv_bfloat16 g_khi[S_LEN * KVD],     g_klo[S_LEN * KVD];
static __device__ __nv_bfloat16 g_vhi[S_LEN * KVD],     g_vlo[S_LEN * KVD];
static __device__ __nv_bfloat16 g_ohi[S_LEN * D_MODEL], g_olo[S_LEN * D_MODEL];

// ---------------------------------------------------------------------------
// Helpers
// ---------------------------------------------------------------------------
__device__ __forceinline__ uint32_t s2u(const void* p) {
    return (uint32_t)__cvta_generic_to_shared(p);
}
__device__ __forceinline__ void cpa(uint32_t s, const void* g) {
    asm volatile("cp.async.cg.shared.global [%0], [%1], 16;\n" :: "r"(s), "l"(g));
}
__device__ __forceinline__ void ldsm4(uint32_t r[4], uint32_t a) {
    asm volatile("ldmatrix.sync.aligned.m8n8.x4.shared.b16 {%0,%1,%2,%3}, [%4];"
                 : "=r"(r[0]), "=r"(r[1]), "=r"(r[2]), "=r"(r[3]) : "r"(a));
}
__device__ __forceinline__ void ldsm4t(uint32_t r[4], uint32_t a) {
    asm volatile("ldmatrix.sync.aligned.m8n8.x4.trans.shared.b16 {%0,%1,%2,%3}, [%4];"
                 : "=r"(r[0]), "=r"(r[1]), "=r"(r[2]), "=r"(r[3]) : "r"(a));
}
__device__ __forceinline__ void mma16816(float c[4], const uint32_t a[4], const uint32_t b[2]) {
    asm volatile(
        "mma.sync.aligned.m16n8k16.row.col.f32.bf16.bf16.f32 "
        "{%0,%1,%2,%3}, {%4,%5,%6,%7}, {%8,%9}, {%0,%1,%2,%3};"
        : "+f"(c[0]), "+f"(c[1]), "+f"(c[2]), "+f"(c[3])
        : "r"(a[0]), "r"(a[1]), "r"(a[2]), "r"(a[3]), "r"(b[0]), "r"(b[1]));
}
// Pack (a,b) -> bf16x2 hi word (lo half = a) + residual bf16x2 lo word.
__device__ __forceinline__ void pack2(float a, float b, uint32_t& hi, uint32_t& lo) {
    uint32_t hpk;
    asm("cvt.rn.bf16x2.f32 %0, %1, %2;" : "=r"(hpk) : "f"(b), "f"(a));
    const float ra = a - __uint_as_float(hpk << 16);
    const float rb = b - __uint_as_float(hpk & 0xffff0000u);
    uint32_t lpk;
    asm("cvt.rn.bf16x2.f32 %0, %1, %2;" : "=r"(lpk) : "f"(rb), "f"(ra));
    hi = hpk; lo = lpk;
}

// ---------------------------------------------------------------------------
// Split fp32 -> (bf16 hi, bf16 lo), lo = bf16(x - float(hi)). n4 = count/4.
// ---------------------------------------------------------------------------
__global__ void split_k(const float* __restrict__ in, __nv_bfloat16* __restrict__ hi,
                        __nv_bfloat16* __restrict__ lo, int n4)
{
    const int i = blockIdx.x * 256 + threadIdx.x;
    if (i >= n4) return;
    const float4 v = ((const float4*)in)[i];
    const float x[4] = {v.x, v.y, v.z, v.w};
    union { __nv_bfloat16 h[4]; uint2 u; } H, L;
    #pragma unroll
    for (int k = 0; k < 4; ++k) {
        H.h[k] = __float2bfloat16(x[k]);
        L.h[k] = __float2bfloat16(x[k] - __bfloat162float(H.h[k]));
    }
    ((uint2*)hi)[i] = H.u;
    ((uint2*)lo)[i] = L.u;
}

// ---------------------------------------------------------------------------
// Tensor-core GEMM, 2-term split: C = Ah*Bh + Ah*Bl + Al*Bh (fp32 acc).
// 128x128x32 tile, 256 threads (4m x 2n warps). Optional RoPE epilogue.
// SPLITOUT: write bf16 hi/lo pair instead of fp32.
// ---------------------------------------------------------------------------
#define GEMM_SMEM ((2*128*40*2 + 2*32*136*2) * 2)   // 75776 bytes

template <bool ROPE, bool SPLITOUT>
__global__ void __launch_bounds__(256) gemm_mma(
    const __nv_bfloat16* __restrict__ Ah, const __nv_bfloat16* __restrict__ Al,
    const __nv_bfloat16* __restrict__ Bh, const __nv_bfloat16* __restrict__ Bl,
    float* __restrict__ C, __nv_bfloat16* __restrict__ Chi, __nv_bfloat16* __restrict__ Clo,
    int M, int N, int K,
    const float* __restrict__ fc, const float* __restrict__ fs)
{
    extern __shared__ __nv_bfloat16 smem[];
    __nv_bfloat16* As_h = smem;                    // [2][128][40]
    __nv_bfloat16* As_l = As_h + 2 * 128 * 40;
    __nv_bfloat16* Bs_h = As_l + 2 * 128 * 40;     // [2][32][136]
    __nv_bfloat16* Bs_l = Bs_h + 2 * 32 * 136;

    const int tid  = threadIdx.x;
    const int lane = tid & 31;
    const int wid  = tid >> 5;
    const int wm   = wid & 3;
    const int wn   = wid >> 2;
    const int row0 = blockIdx.y * 128;
    const int n0   = blockIdx.x * 128;

    auto prefetch = [&](int t, int buf) {
        const int k0 = t * 32;
        #pragma unroll
        for (int p = 0; p < 2; ++p) {
            const int e = tid + p * 256;
            const int r = e >> 2, c = (e & 3) * 8;
            const size_t g = (size_t)(row0 + r) * K + k0 + c;
            const int so = (buf * 128 + r) * 40 + c;
            cpa(s2u(As_h + so), Ah + g);
            cpa(s2u(As_l + so), Al + g);
        }
        #pragma unroll
        for (int p = 0; p < 2; ++p) {
            const int e = tid + p * 256;
            const int r = e >> 4, c = (e & 15) * 8;
            const size_t g = (size_t)(k0 + r) * N + n0 + c;
            const int so = (buf * 32 + r) * 136 + c;
            cpa(s2u(Bs_h + so), Bh + g);
            cpa(s2u(Bs_l + so), Bl + g);
        }
        asm volatile("cp.async.commit_group;\n");
    };

    float acc[2][8][4];
    #pragma unroll
    for (int i = 0; i < 2; ++i)
        #pragma unroll
        for (int j = 0; j < 8; ++j)
            #pragma unroll
            for (int q = 0; q < 4; ++q) acc[i][j][q] = 0.f;

    const int T = K / 32;
    prefetch(0, 0);

    for (int t = 0; t < T; ++t) {
        asm volatile("cp.async.wait_group 0;\n");
        __syncthreads();
        if (t + 1 < T) prefetch(t + 1, (t + 1) & 1);

        const int buf = t & 1;
        const __nv_bfloat16* Abh = As_h + buf * 128 * 40;
        const __nv_bfloat16* Abl = As_l + buf * 128 * 40;
        const __nv_bfloat16* Bbh = Bs_h + buf * 32 * 136;
        const __nv_bfloat16* Bbl = Bs_l + buf * 32 * 136;

        #pragma unroll
        for (int kk = 0; kk < 2; ++kk) {
            uint32_t ah[2][4], al[2][4];
            #pragma unroll
            for (int i = 0; i < 2; ++i) {
                const int rr = wm * 32 + i * 16 + (lane & 15);
                const int cc = kk * 16 + ((lane >> 4) << 3);
                ldsm4(ah[i], s2u(Abh + rr * 40 + cc));
                ldsm4(al[i], s2u(Abl + rr * 40 + cc));
            }
            uint32_t bh[8][2], bl[8][2];
            #pragma unroll
            for (int jj = 0; jj < 4; ++jj) {
                const int rr = kk * 16 + (lane & 15);
                const int cc = wn * 64 + jj * 16 + ((lane >> 4) << 3);
                uint32_t r4[4];
                ldsm4t(r4, s2u(Bbh + rr * 136 + cc));
                bh[2*jj][0] = r4[0]; bh[2*jj][1] = r4[1];
                bh[2*jj+1][0] = r4[2]; bh[2*jj+1][1] = r4[3];
                ldsm4t(r4, s2u(Bbl + rr * 136 + cc));
                bl[2*jj][0] = r4[0]; bl[2*jj][1] = r4[1];
                bl[2*jj+1][0] = r4[2]; bl[2*jj+1][1] = r4[3];
            }
            #pragma unroll
            for (int i = 0; i < 2; ++i)
                #pragma unroll
                for (int j = 0; j < 8; ++j) {
                    mma16816(acc[i][j], ah[i], bh[j]);
                    mma16816(acc[i][j], ah[i], bl[j]);
                    mma16816(acc[i][j], al[i], bh[j]);
                }
        }
        __syncthreads();
    }

    const int g  = lane >> 2;
    const int tq = lane & 3;
    #pragma unroll
    for (int i = 0; i < 2; ++i) {
        const int rbase = row0 + wm * 32 + i * 16 + g;
        #pragma unroll
        for (int j = 0; j < 8; ++j) {
            const int col = n0 + wn * 64 + j * 8 + tq * 2;
            float v0 = acc[i][j][0], v1 = acc[i][j][1];
            float v2 = acc[i][j][2], v3 = acc[i][j][3];
            if (ROPE) {
                const int pi = (col & (HD - 1)) >> 1;
                const float c0 = fc[rbase * (HD/2) + pi];
                const float s0 = fs[rbase * (HD/2) + pi];
                const float c1 = fc[(rbase + 8) * (HD/2) + pi];
                const float s1 = fs[(rbase + 8) * (HD/2) + pi];
                float t0 = v0, t1 = v1;
                v0 = t0 * c0 - t1 * s0;  v1 = t0 * s0 + t1 * c0;
                t0 = v2; t1 = v3;
                v2 = t0 * c1 - t1 * s1;  v3 = t0 * s1 + t1 * c1;
            }
            if (SPLITOUT) {
                uint32_t hp, lp;
                pack2(v0, v1, hp, lp);
                *(uint32_t*)&Chi[(size_t)rbase * N + col] = hp;
                *(uint32_t*)&Clo[(size_t)rbase * N + col] = lp;
                pack2(v2, v3, hp, lp);
                *(uint32_t*)&Chi[(size_t)(rbase + 8) * N + col] = hp;
                *(uint32_t*)&Clo[(size_t)(rbase + 8) * N + col] = lp;
            } else {
                *(float2*)&C[(size_t)rbase * N + col]       = make_float2(v0, v1);
                *(float2*)&C[(size_t)(rbase + 8) * N + col] = make_float2(v2, v3);
            }
        }
    }
}

// ---------------------------------------------------------------------------
// Tensorized flash attention. CTA = (head, 64 q rows), 4 warps, warp owns 16
// rows. 3-term split mma for QK^T and PV. Warp-local online softmax (regs).
// Smem: Qh/Ql/Kh/Kl/Vh/Vl [64][136] bf16 = 104448 B -> 2 CTAs/SM.
// ---------------------------------------------------------------------------
#define ATTN_SMEM (6 * 64 * 136 * 2)

__global__ void __launch_bounds__(128, 2) attn_mma(
    const __nv_bfloat16* __restrict__ qhi, const __nv_bfloat16* __restrict__ qlo,
    const __nv_bfloat16* __restrict__ khi, const __nv_bfloat16* __restrict__ klo,
    const __nv_bfloat16* __restrict__ vhi, const __nv_bfloat16* __restrict__ vlo,
    __nv_bfloat16* __restrict__ ohi, __nv_bfloat16* __restrict__ olo)
{
    extern __shared__ __nv_bfloat16 as_[];
    __nv_bfloat16* Qh = as_;
    __nv_bfloat16* Ql = Qh + 64 * 136;
    __nv_bfloat16* Kh = Ql + 64 * 136;
    __nv_bfloat16* Kl = Kh + 64 * 136;
    __nv_bfloat16* Vh = Kl + 64 * 136;
    __nv_bfloat16* Vl = Vh + 64 * 136;

    const int tid  = threadIdx.x;
    const int lane = tid & 31;
    const int w    = tid >> 5;
    const int qt   = (int)gridDim.x - 1 - (int)blockIdx.x;   // heavy tiles first
    const int h    = blockIdx.y;
    const int hk   = h >> 2;
    const int q0   = qt * 64;
    const int g    = lane >> 2;
    const int qd   = lane & 3;
    const int row0g = q0 + w * 16 + g;
    const int row1g = row0g + 8;
    const float scale = 0.08838834764831845f;   // 1/sqrt(128)

    // Load Q tile (hi/lo) once.
    #pragma unroll
    for (int p = 0; p < 8; ++p) {
        const int e = tid + p * 128, r = e >> 4, c8 = (e & 15) * 8;
        const size_t go = (size_t)(q0 + r) * D_MODEL + h * HD + c8;
        cpa(s2u(Qh + r * 136 + c8), qhi + go);
        cpa(s2u(Ql + r * 136 + c8), qlo + go);
    }
    asm volatile("cp.async.commit_group;\n");

    float accO[16][4];
    #pragma unroll
    for (int d = 0; d < 16; ++d)
        #pragma unroll
        for (int e = 0; e < 4; ++e) accO[d][e] = 0.f;
    float m0 = -1e30f, m1 = -1e30f, l0 = 0.f, l1 = 0.f;

    for (int kt = 0; kt <= qt; ++kt) {
        __syncthreads();   // previous iteration done reading K/V
        #pragma unroll
        for (int p = 0; p < 8; ++p) {
            const int e = tid + p * 128, r = e >> 4, c8 = (e & 15) * 8;
            const size_t go = (size_t)(kt * 64 + r) * KVD + hk * HD + c8;
            const int so = r * 136 + c8;
            cpa(s2u(Kh + so), khi + go);
            cpa(s2u(Kl + so), klo + go);
            cpa(s2u(Vh + so), vhi + go);
            cpa(s2u(Vl + so), vlo + go);
        }
        asm volatile("cp.async.commit_group;\ncp.async.wait_group 0;\n");
        __syncthreads();

        // ---- scores S[16,64] = Q . K^T (3-term split) ----
        float sc[8][4];
        #pragma unroll
        for (int t = 0; t < 8; ++t)
            #pragma unroll
            for (int e = 0; e < 4; ++e) sc[t][e] = 0.f;

        #pragma unroll
        for (int kk = 0; kk < 8; ++kk) {
            uint32_t qa[4], qb[4];
            const int ra = w * 16 + (lane & 15);
            const int cc = kk * 16 + ((lane >> 4) << 3);
            ldsm4(qa, s2u(Qh + ra * 136 + cc));
            ldsm4(qb, s2u(Ql + ra * 136 + cc));
            #pragma unroll
            for (int jp = 0; jp < 4; ++jp) {
                uint32_t r4[4], s4[4];
                const int rb = jp * 16 + (lane & 15);
                ldsm4(r4, s2u(Kh + rb * 136 + cc));
                ldsm4(s4, s2u(Kl + rb * 136 + cc));
                uint32_t bh0[2] = {r4[0], r4[2]}, bh1[2] = {r4[1], r4[3]};
                uint32_t bl0[2] = {s4[0], s4[2]}, bl1[2] = {s4[1], s4[3]};
                mma16816(sc[2*jp],   qa, bh0);
                mma16816(sc[2*jp],   qa, bl0);
                mma16816(sc[2*jp],   qb, bh0);
                mma16816(sc[2*jp+1], qa, bh1);
                mma16816(sc[2*jp+1], qa, bl1);
                mma16816(sc[2*jp+1], qb, bh1);
            }
        }

        // ---- scale + causal mask ----
        const bool diag = (kt == qt);
        #pragma unroll
        for (int t = 0; t < 8; ++t)
            #pragma unroll
            for (int e = 0; e < 4; ++e) {
                float v = sc[t][e] * scale;
                if (diag) {
                    const int col = kt * 64 + t * 8 + qd * 2 + (e & 1);
                    const int row = (e < 2) ? row0g : row1g;
                    if (col > row) v = -1e30f;
                }
                sc[t][e] = v;
            }

        // ---- online softmax (rows g and g+8; quad lanes share a row) ----
        float tm0 = -1e30f, tm1 = -1e30f;
        #pragma unroll
        for (int t = 0; t < 8; ++t) {
            tm0 = fmaxf(tm0, fmaxf(sc[t][0], sc[t][1]));
            tm1 = fmaxf(tm1, fmaxf(sc[t][2], sc[t][3]));
        }
        #pragma unroll
        for (int o = 1; o <= 2; o <<= 1) {
            tm0 = fmaxf(tm0, __shfl_xor_sync(0xffffffffu, tm0, o));
            tm1 = fmaxf(tm1, __shfl_xor_sync(0xffffffffu, tm1, o));
        }
        const float m0n = fmaxf(m0, tm0), m1n = fmaxf(m1, tm1);
        const float f0 = __expf(m0 - m0n), f1 = __expf(m1 - m1n);

        float rs0 = 0.f, rs1 = 0.f;
        #pragma unroll
        for (int t = 0; t < 8; ++t) {
            sc[t][0] = __expf(sc[t][0] - m0n); rs0 += sc[t][0];
            sc[t][1] = __expf(sc[t][1] - m0n); rs0 += sc[t][1];
            sc[t][2] = __expf(sc[t][2] - m1n); rs1 += sc[t][2];
            sc[t][3] = __expf(sc[t][3] - m1n); rs1 += sc[t][3];
        }
        #pragma unroll
        for (int o = 1; o <= 2; o <<= 1) {
            rs0 += __shfl_xor_sync(0xffffffffu, rs0, o);
            rs1 += __shfl_xor_sync(0xffffffffu, rs1, o);
        }
        l0 = l0 * f0 + rs0;  l1 = l1 * f1 + rs1;
        m0 = m0n;            m1 = m1n;

        #pragma unroll
        for (int d = 0; d < 16; ++d) {
            accO[d][0] *= f0; accO[d][1] *= f0;
            accO[d][2] *= f1; accO[d][3] *= f1;
        }

        // ---- pack P (score C-frag -> A-frag, hi/lo split) ----
        uint32_t ph[4][4], pl[4][4];
        #pragma unroll
        for (int j = 0; j < 4; ++j) {
            pack2(sc[2*j][0],   sc[2*j][1],   ph[j][0], pl[j][0]);
            pack2(sc[2*j][2],   sc[2*j][3],   ph[j][1], pl[j][1]);
            pack2(sc[2*j+1][0], sc[2*j+1][1], ph[j][2], pl[j][2]);
            pack2(sc[2*j+1][2], sc[2*j+1][3], ph[j][3], pl[j][3]);
        }

        // ---- O += P @ V (3-term split) ----
        #pragma unroll
        for (int dp = 0; dp < 8; ++dp) {
            const int ccv = dp * 16 + ((lane >> 4) << 3);
            #pragma unroll
            for (int j = 0; j < 4; ++j) {
                uint32_t r4[4], s4[4];
                const int rv = j * 16 + (lane & 15);
                ldsm4t(r4, s2u(Vh + rv * 136 + ccv));
                ldsm4t(s4, s2u(Vl + rv * 136 + ccv));
                uint32_t bh0[2] = {r4[0], r4[1]}, bh1[2] = {r4[2], r4[3]};
                uint32_t bl0[2] = {s4[0], s4[1]}, bl1[2] = {s4[2], s4[3]};
                mma16816(accO[2*dp],   ph[j], bh0);
                mma16816(accO[2*dp],   ph[j], bl0);
                mma16816(accO[2*dp],   pl[j], bh0);
                mma16816(accO[2*dp+1], ph[j], bh1);
                mma16816(accO[2*dp+1], ph[j], bl1);
                mma16816(accO[2*dp+1], pl[j], bh1);
            }
        }
    }

    // ---- normalize + split-write output ----
    const float i0 = 1.f / l0, i1 = 1.f / l1;
    #pragma unroll
    for (int dt = 0; dt < 16; ++dt) {
        const int col = h * HD + dt * 8 + qd * 2;
        uint32_t hp, lp;
        pack2(accO[dt][0] * i0, accO[dt][1] * i0, hp, lp);
        *(uint32_t*)&ohi[(size_t)row0g * D_MODEL + col] = hp;
        *(uint32_t*)&olo[(size_t)row0g * D_MODEL + col] = lp;
        pack2(accO[dt][2] * i1, accO[dt][3] * i1, hp, lp);
        *(uint32_t*)&ohi[(size_t)row1g * D_MODEL + col] = hp;
        *(uint32_t*)&olo[(size_t)row1g * D_MODEL + col] = lp;
    }
}

// ---------------------------------------------------------------------------
// Launch. Graph-capturable, allocation-free.
// ---------------------------------------------------------------------------
extern "C" void kernel_launch(void* const* d_in, const int* in_sizes, int n_in,
                              void* d_out, int out_size)
{
    const float* x  = (const float*)d_in[0];
    const float* wq = (const float*)d_in[1];
    const float* wk = (const float*)d_in[2];
    const float* wv = (const float*)d_in[3];
    const float* wo = (const float*)d_in[4];
    const float* fc = (const float*)d_in[5];
    const float* fs = (const float*)d_in[6];
    float* out = (float*)d_out;

    __nv_bfloat16 *xhi, *xlo, *wqhi, *wqlo, *wkhi, *wklo, *wvhi, *wvlo, *wohi, *wolo;
    __nv_bfloat16 *qhi, *qlo, *khi, *klo, *vhi, *vlo, *ohi, *olo;
    cudaGetSymbolAddress((void**)&xhi, g_xhi);   cudaGetSymbolAddress((void**)&xlo, g_xlo);
    cudaGetSymbolAddress((void**)&wqhi, g_wqhi); cudaGetSymbolAddress((void**)&wqlo, g_wqlo);
    cudaGetSymbolAddress((void**)&wkhi, g_wkhi); cudaGetSymbolAddress((void**)&wklo, g_wklo);
    cudaGetSymbolAddress((void**)&wvhi, g_wvhi); cudaGetSymbolAddress((void**)&wvlo, g_wvlo);
    cudaGetSymbolAddress((void**)&wohi, g_wohi); cudaGetSymbolAddress((void**)&wolo, g_wolo);
    cudaGetSymbolAddress((void**)&qhi, g_qhi);   cudaGetSymbolAddress((void**)&qlo, g_qlo);
    cudaGetSymbolAddress((void**)&khi, g_khi);   cudaGetSymbolAddress((void**)&klo, g_klo);
    cudaGetSymbolAddress((void**)&vhi, g_vhi);   cudaGetSymbolAddress((void**)&vlo, g_vlo);
    cudaGetSymbolAddress((void**)&ohi, g_ohi);   cudaGetSymbolAddress((void**)&olo, g_olo);

    cudaFuncSetAttribute((const void*)gemm_mma<true,  true >, cudaFuncAttributeMaxDynamicSharedMemorySize, GEMM_SMEM);
    cudaFuncSetAttribute((const void*)gemm_mma<false, true >, cudaFuncAttributeMaxDynamicSharedMemorySize, GEMM_SMEM);
    cudaFuncSetAttribute((const void*)gemm_mma<false, false>, cudaFuncAttributeMaxDynamicSharedMemorySize, GEMM_SMEM);
    cudaFuncSetAttribute((const void*)attn_mma, cudaFuncAttributeMaxDynamicSharedMemorySize, ATTN_SMEM);

    // Input/weight splits
    {
        int n4 = S_LEN * D_MODEL / 4;
        split_k<<<(n4 + 255) / 256, 256>>>(x, xhi, xlo, n4);
        n4 = D_MODEL * D_MODEL / 4;
        split_k<<<(n4 + 255) / 256, 256>>>(wq, wqhi, wqlo, n4);
        split_k<<<(n4 + 255) / 256, 256>>>(wo, wohi, wolo, n4);
        n4 = D_MODEL * KVD / 4;
        split_k<<<(n4 + 255) / 256, 256>>>(wk, wkhi, wklo, n4);
        split_k<<<(n4 + 255) / 256, 256>>>(wv, wvhi, wvlo, n4);
    }

    dim3 blk(256);
    // Q = x @ wq (+RoPE), split output
    gemm_mma<true,  true ><<<dim3(D_MODEL / 128, S_LEN / 128), blk, GEMM_SMEM>>>(
        xhi, xlo, wqhi, wqlo, nullptr, qhi, qlo, S_LEN, D_MODEL, D_MODEL, fc, fs);
    // K = x @ wk (+RoPE), split output
    gemm_mma<true,  true ><<<dim3(KVD / 128, S_LEN / 128), blk, GEMM_SMEM>>>(
        xhi, xlo, wkhi, wklo, nullptr, khi, klo, S_LEN, KVD, D_MODEL, fc, fs);
    // V = x @ wv, split output
    gemm_mma<false, true ><<<dim3(KVD / 128, S_LEN / 128), blk, GEMM_SMEM>>>(
        xhi, xlo, wvhi, wvlo, nullptr, vhi, vlo, S_LEN, KVD, D_MODEL, nullptr, nullptr);
    // Attention (tensorized), split output
    attn_mma<<<dim3(S_LEN / 64, NH), dim3(128), ATTN_SMEM>>>(
        qhi, qlo, khi, klo, vhi, vlo, ohi, olo);
    // out = o @ wo, fp32 output
    gemm_mma<false, false><<<dim3(D_MODEL / 128, S_LEN / 128), blk, GEMM_SMEM>>>(
        ohi, olo, wohi, wolo, out, nullptr, nullptr, S_LEN, D_MODEL, D_MODEL, nullptr, nullptr);
}

// round 14
// speedup vs baseline: 3.5795x; 1.0040x over previous
#include <cuda_runtime.h>
#include <cuda_bf16.h>
#include <cstdint>
#include <cstddef>

#define S_LEN   2048
#define D_MODEL 4096
#define NH      32
#define NKV     8
#define HD      128
#define KVD     (NKV * HD)   // 1024

// ---------------------------------------------------------------------------
// Scratch (__device__ globals; no allocations allowed anywhere).
// ---------------------------------------------------------------------------
static __device__ __nv_bfloat16 g_xhi[S_LEN * D_MODEL],  g_xlo[S_LEN * D_MODEL];
static __device__ __nv_bfloat16 g_wqhi[D_MODEL * D_MODEL], g_wqlo[D_MODEL * D_MODEL];
static __device__ __nv_bfloat16 g_wkhi[D_MODEL * KVD],   g_wklo[D_MODEL * KVD];
static __device__ __nv_bfloat16 g_wvhi[D_MODEL * KVD],   g_wvlo[D_MODEL * KVD];
static __device__ __nv_bfloat16 g_wohi[D_MODEL * D_MODEL], g_wolo[D_MODEL * D_MODEL];

static __device__ __nv_bfloat16 g_qhi[S_LEN * D_MODEL], g_qlo[S_LEN * D_MODEL];
static __device__ __nv_bfloat16 g_khi[S_LEN * KVD],     g_klo[S_LEN * KVD];
static __device__ __nv_bfloat16 g_vhi[S_LEN * KVD],     g_vlo[S_LEN * KVD];
static __device__ __nv_bfloat16 g_ohi[S_LEN * D_MODEL], g_olo[S_LEN * D_MODEL];

// ---------------------------------------------------------------------------
// Helpers
// ---------------------------------------------------------------------------
__device__ __forceinline__ uint32_t s2u(const void* p) {
    return (uint32_t)__cvta_generic_to_shared(p);
}
__device__ __forceinline__ void cpa(uint32_t s, const void* g) {
    asm volatile("cp.async.cg.shared.global [%0], [%1], 16;\n" :: "r"(s), "l"(g));
}
__device__ __forceinline__ void ldsm4(uint32_t r[4], uint32_t a) {
    asm volatile("ldmatrix.sync.aligned.m8n8.x4.shared.b16 {%0,%1,%2,%3}, [%4];"
                 : "=r"(r[0]), "=r"(r[1]), "=r"(r[2]), "=r"(r[3]) : "r"(a));
}
__device__ __forceinline__ void ldsm4t(uint32_t r[4], uint32_t a) {
    asm volatile("ldmatrix.sync.aligned.m8n8.x4.trans.shared.b16 {%0,%1,%2,%3}, [%4];"
                 : "=r"(r[0]), "=r"(r[1]), "=r"(r[2]), "=r"(r[3]) : "r"(a));
}
__device__ __forceinline__ void mma16816(float c[4], const uint32_t a[4], const uint32_t b[2]) {
    asm volatile(
        "mma.sync.aligned.m16n8k16.row.col.f32.bf16.bf16.f32 "
        "{%0,%1,%2,%3}, {%4,%5,%6,%7}, {%8,%9}, {%0,%1,%2,%3};"
        : "+f"(c[0]), "+f"(c[1]), "+f"(c[2]), "+f"(c[3])
        : "r"(a[0]), "r"(a[1]), "r"(a[2]), "r"(a[3]), "r"(b[0]), "r"(b[1]));
}
// Pack (a,b) -> bf16x2 hi word (lo half = a) + residual bf16x2 lo word.
__device__ __forceinline__ void pack2(float a, float b, uint32_t& hi, uint32_t& lo) {
    uint32_t hpk;
    asm("cvt.rn.bf16x2.f32 %0, %1, %2;" : "=r"(hpk) : "f"(b), "f"(a));
    const float ra = a - __uint_as_float(hpk << 16);
    const float rb = b - __uint_as_float(hpk & 0xffff0000u);
    uint32_t lpk;
    asm("cvt.rn.bf16x2.f32 %0, %1, %2;" : "=r"(lpk) : "f"(rb), "f"(ra));
    hi = hpk; lo = lpk;
}

// ---------------------------------------------------------------------------
// Split fp32 -> (bf16 hi, bf16 lo), lo = bf16(x - float(hi)). n4 = count/4.
// ---------------------------------------------------------------------------
__global__ void split_k(const float* __restrict__ in, __nv_bfloat16* __restrict__ hi,
                        __nv_bfloat16* __restrict__ lo, int n4)
{
    const int i = blockIdx.x * 256 + threadIdx.x;
    if (i >= n4) return;
    const float4 v = ((const float4*)in)[i];
    const float x[4] = {v.x, v.y, v.z, v.w};
    union { __nv_bfloat16 h[4]; uint2 u; } H, L;
    #pragma unroll
    for (int k = 0; k < 4; ++k) {
        H.h[k] = __float2bfloat16(x[k]);
        L.h[k] = __float2bfloat16(x[k] - __bfloat162float(H.h[k]));
    }
    ((uint2*)hi)[i] = H.u;
    ((uint2*)lo)[i] = L.u;
}

// ---------------------------------------------------------------------------
// Tensor-core GEMM, 2-term split: C = Ah*Bh + Ah*Bl + Al*Bh (fp32 acc).
// 128x128x32 tile, 256 threads (4m x 2n warps). Optional RoPE epilogue.
// SPLITOUT: write bf16 hi/lo pair instead of fp32.
// ---------------------------------------------------------------------------
#define GEMM_SMEM ((2*128*40*2 + 2*32*136*2) * 2)   // 75776 bytes

template <bool ROPE, bool SPLITOUT>
__global__ void __launch_bounds__(256) gemm_mma(
    const __nv_bfloat16* __restrict__ Ah, const __nv_bfloat16* __restrict__ Al,
    const __nv_bfloat16* __restrict__ Bh, const __nv_bfloat16* __restrict__ Bl,
    float* __restrict__ C, __nv_bfloat16* __restrict__ Chi, __nv_bfloat16* __restrict__ Clo,
    int M, int N, int K,
    const float* __restrict__ fc, const float* __restrict__ fs)
{
    extern __shared__ __nv_bfloat16 smem[];
    __nv_bfloat16* As_h = smem;                    // [2][128][40]
    __nv_bfloat16* As_l = As_h + 2 * 128 * 40;
    __nv_bfloat16* Bs_h = As_l + 2 * 128 * 40;     // [2][32][136]
    __nv_bfloat16* Bs_l = Bs_h + 2 * 32 * 136;

    const int tid  = threadIdx.x;
    const int lane = tid & 31;
    const int wid  = tid >> 5;
    const int wm   = wid & 3;
    const int wn   = wid >> 2;
    const int row0 = blockIdx.y * 128;
    const int n0   = blockIdx.x * 128;

    auto prefetch = [&](int t, int buf) {
        const int k0 = t * 32;
        #pragma unroll
        for (int p = 0; p < 2; ++p) {
            const int e = tid + p * 256;
            const int r = e >> 2, c = (e & 3) * 8;
            const size_t g = (size_t)(row0 + r) * K + k0 + c;
            const int so = (buf * 128 + r) * 40 + c;
            cpa(s2u(As_h + so), Ah + g);
            cpa(s2u(As_l + so), Al + g);
        }
        #pragma unroll
        for (int p = 0; p < 2; ++p) {
            const int e = tid + p * 256;
            const int r = e >> 4, c = (e & 15) * 8;
            const size_t g = (size_t)(k0 + r) * N + n0 + c;
            const int so = (buf * 32 + r) * 136 + c;
            cpa(s2u(Bs_h + so), Bh + g);
            cpa(s2u(Bs_l + so), Bl + g);
        }
        asm volatile("cp.async.commit_group;\n");
    };

    float acc[2][8][4];
    #pragma unroll
    for (int i = 0; i < 2; ++i)
        #pragma unroll
        for (int j = 0; j < 8; ++j)
            #pragma unroll
            for (int q = 0; q < 4; ++q) acc[i][j][q] = 0.f;

    const int T = K / 32;
    prefetch(0, 0);

    for (int t = 0; t < T; ++t) {
        asm volatile("cp.async.wait_group 0;\n");
        __syncthreads();
        if (t + 1 < T) prefetch(t + 1, (t + 1) & 1);

        const int buf = t & 1;
        const __nv_bfloat16* Abh = As_h + buf * 128 * 40;
        const __nv_bfloat16* Abl = As_l + buf * 128 * 40;
        const __nv_bfloat16* Bbh = Bs_h + buf * 32 * 136;
        const __nv_bfloat16* Bbl = Bs_l + buf * 32 * 136;

        #pragma unroll
        for (int kk = 0; kk < 2; ++kk) {
            uint32_t ah[2][4], al[2][4];
            #pragma unroll
            for (int i = 0; i < 2; ++i) {
                const int rr = wm * 32 + i * 16 + (lane & 15);
                const int cc = kk * 16 + ((lane >> 4) << 3);
                ldsm4(ah[i], s2u(Abh + rr * 40 + cc));
                ldsm4(al[i], s2u(Abl + rr * 40 + cc));
            }
            uint32_t bh[8][2], bl[8][2];
            #pragma unroll
            for (int jj = 0; jj < 4; ++jj) {
                const int rr = kk * 16 + (lane & 15);
                const int cc = wn * 64 + jj * 16 + ((lane >> 4) << 3);
                uint32_t r4[4];
                ldsm4t(r4, s2u(Bbh + rr * 136 + cc));
                bh[2*jj][0] = r4[0]; bh[2*jj][1] = r4[1];
                bh[2*jj+1][0] = r4[2]; bh[2*jj+1][1] = r4[3];
                ldsm4t(r4, s2u(Bbl + rr * 136 + cc));
                bl[2*jj][0] = r4[0]; bl[2*jj][1] = r4[1];
                bl[2*jj+1][0] = r4[2]; bl[2*jj+1][1] = r4[3];
            }
            #pragma unroll
            for (int i = 0; i < 2; ++i)
                #pragma unroll
                for (int j = 0; j < 8; ++j) {
                    mma16816(acc[i][j], ah[i], bh[j]);
                    mma16816(acc[i][j], ah[i], bl[j]);
                    mma16816(acc[i][j], al[i], bh[j]);
                }
        }
        __syncthreads();
    }

    const int g  = lane >> 2;
    const int tq = lane & 3;
    #pragma unroll
    for (int i = 0; i < 2; ++i) {
        const int rbase = row0 + wm * 32 + i * 16 + g;
        #pragma unroll
        for (int j = 0; j < 8; ++j) {
            const int col = n0 + wn * 64 + j * 8 + tq * 2;
            float v0 = acc[i][j][0], v1 = acc[i][j][1];
            float v2 = acc[i][j][2], v3 = acc[i][j][3];
            if (ROPE) {
                const int pi = (col & (HD - 1)) >> 1;
                const float c0 = fc[rbase * (HD/2) + pi];
                const float s0 = fs[rbase * (HD/2) + pi];
                const float c1 = fc[(rbase + 8) * (HD/2) + pi];
                const float s1 = fs[(rbase + 8) * (HD/2) + pi];
                float t0 = v0, t1 = v1;
                v0 = t0 * c0 - t1 * s0;  v1 = t0 * s0 + t1 * c0;
                t0 = v2; t1 = v3;
                v2 = t0 * c1 - t1 * s1;  v3 = t0 * s1 + t1 * c1;
            }
            if (SPLITOUT) {
                uint32_t hp, lp;
                pack2(v0, v1, hp, lp);
                *(uint32_t*)&Chi[(size_t)rbase * N + col] = hp;
                *(uint32_t*)&Clo[(size_t)rbase * N + col] = lp;
                pack2(v2, v3, hp, lp);
                *(uint32_t*)&Chi[(size_t)(rbase + 8) * N + col] = hp;
                *(uint32_t*)&Clo[(size_t)(rbase + 8) * N + col] = lp;
            } else {
                *(float2*)&C[(size_t)rbase * N + col]       = make_float2(v0, v1);
                *(float2*)&C[(size_t)(rbase + 8) * N + col] = make_float2(v2, v3);
            }
        }
    }
}

// ---------------------------------------------------------------------------
// Tensorized flash attention. CTA = (head, 64 q rows), 4 warps, warp owns 16
// rows. 3-term split mma for QK^T and PV. Warp-local online softmax (regs).
// Smem: Qh/Ql/Kh/Kl/Vh/Vl [64][136] bf16 = 104448 B -> 2 CTAs/SM.
// ---------------------------------------------------------------------------
#define ATTN_SMEM (6 * 64 * 136 * 2)

__global__ void __launch_bounds__(128, 2) attn_mma(
    const __nv_bfloat16* __restrict__ qhi, const __nv_bfloat16* __restrict__ qlo,
    const __nv_bfloat16* __restrict__ khi, const __nv_bfloat16* __restrict__ klo,
    const __nv_bfloat16* __restrict__ vhi, const __nv_bfloat16* __restrict__ vlo,
    __nv_bfloat16* __restrict__ ohi, __nv_bfloat16* __restrict__ olo)
{
    extern __shared__ __nv_bfloat16 as_[];
    __nv_bfloat16* Qh = as_;
    __nv_bfloat16* Ql = Qh + 64 * 136;
    __nv_bfloat16* Kh = Ql + 64 * 136;
    __nv_bfloat16* Kl = Kh + 64 * 136;
    __nv_bfloat16* Vh = Kl + 64 * 136;
    __nv_bfloat16* Vl = Vh + 64 * 136;

    const int tid  = threadIdx.x;
    const int lane = tid & 31;
    const int w    = tid >> 5;
    const int qt   = (int)gridDim.x - 1 - (int)blockIdx.x;   // heavy tiles first
    const int h    = blockIdx.y;
    const int hk   = h >> 2;
    const int q0   = qt * 64;
    const int g    = lane >> 2;
    const int qd   = lane & 3;
    const int row0g = q0 + w * 16 + g;
    const int row1g = row0g + 8;
    const float scale = 0.08838834764831845f;   // 1/sqrt(128)

    // Load Q tile (hi/lo) once.
    #pragma unroll
    for (int p = 0; p < 8; ++p) {
        const int e = tid + p * 128, r = e >> 4, c8 = (e & 15) * 8;
        const size_t go = (size_t)(q0 + r) * D_MODEL + h * HD + c8;
        cpa(s2u(Qh + r * 136 + c8), qhi + go);
        cpa(s2u(Ql + r * 136 + c8), qlo + go);
    }
    asm volatile("cp.async.commit_group;\n");

    float accO[16][4];
    #pragma unroll
    for (int d = 0; d < 16; ++d)
        #pragma unroll
        for (int e = 0; e < 4; ++e) accO[d][e] = 0.f;
    float m0 = -1e30f, m1 = -1e30f, l0 = 0.f, l1 = 0.f;

    for (int kt = 0; kt <= qt; ++kt) {
        __syncthreads();   // previous iteration done reading K/V
        #pragma unroll
        for (int p = 0; p < 8; ++p) {
            const int e = tid + p * 128, r = e >> 4, c8 = (e & 15) * 8;
            const size_t go = (size_t)(kt * 64 + r) * KVD + hk * HD + c8;
            const int so = r * 136 + c8;
            cpa(s2u(Kh + so), khi + go);
            cpa(s2u(Kl + so), klo + go);
            cpa(s2u(Vh + so), vhi + go);
            cpa(s2u(Vl + so), vlo + go);
        }
        asm volatile("cp.async.commit_group;\ncp.async.wait_group 0;\n");
        __syncthreads();

        // ---- scores S[16,64] = Q . K^T (3-term split) ----
        float sc[8][4];
        #pragma unroll
        for (int t = 0; t < 8; ++t)
            #pragma unroll
            for (int e = 0; e < 4; ++e) sc[t][e] = 0.f;

        #pragma unroll
        for (int kk = 0; kk < 8; ++kk) {
            uint32_t qa[4], qb[4];
            const int ra = w * 16 + (lane & 15);
            const int cc = kk * 16 + ((lane >> 4) << 3);
            ldsm4(qa, s2u(Qh + ra * 136 + cc));
            ldsm4(qb, s2u(Ql + ra * 136 + cc));
            #pragma unroll
            for (int jp = 0; jp < 4; ++jp) {
                uint32_t r4[4], s4[4];
                const int rb = jp * 16 + (lane & 15);
                ldsm4(r4, s2u(Kh + rb * 136 + cc));
                ldsm4(s4, s2u(Kl + rb * 136 + cc));
                uint32_t bh0[2] = {r4[0], r4[2]}, bh1[2] = {r4[1], r4[3]};
                uint32_t bl0[2] = {s4[0], s4[2]}, bl1[2] = {s4[1], s4[3]};
                mma16816(sc[2*jp],   qa, bh0);
                mma16816(sc[2*jp],   qa, bl0);
                mma16816(sc[2*jp],   qb, bh0);
                mma16816(sc[2*jp+1], qa, bh1);
                mma16816(sc[2*jp+1], qa, bl1);
                mma16816(sc[2*jp+1], qb, bh1);
            }
        }

        // ---- scale + causal mask ----
        const bool diag = (kt == qt);
        #pragma unroll
        for (int t = 0; t < 8; ++t)
            #pragma unroll
            for (int e = 0; e < 4; ++e) {
                float v = sc[t][e] * scale;
                if (diag) {
                    const int col = kt * 64 + t * 8 + qd * 2 + (e & 1);
                    const int row = (e < 2) ? row0g : row1g;
                    if (col > row) v = -1e30f;
                }
                sc[t][e] = v;
            }

        // ---- online softmax (rows g and g+8; quad lanes share a row) ----
        float tm0 = -1e30f, tm1 = -1e30f;
        #pragma unroll
        for (int t = 0; t < 8; ++t) {
            tm0 = fmaxf(tm0, fmaxf(sc[t][0], sc[t][1]));
            tm1 = fmaxf(tm1, fmaxf(sc[t][2], sc[t][3]));
        }
        #pragma unroll
        for (int o = 1; o <= 2; o <<= 1) {
            tm0 = fmaxf(tm0, __shfl_xor_sync(0xffffffffu, tm0, o));
            tm1 = fmaxf(tm1, __shfl_xor_sync(0xffffffffu, tm1, o));
        }
        const float m0n = fmaxf(m0, tm0), m1n = fmaxf(m1, tm1);
        const float f0 = __expf(m0 - m0n), f1 = __expf(m1 - m1n);

        float rs0 = 0.f, rs1 = 0.f;
        #pragma unroll
        for (int t = 0; t < 8; ++t) {
            sc[t][0] = __expf(sc[t][0] - m0n); rs0 += sc[t][0];
            sc[t][1] = __expf(sc[t][1] - m0n); rs0 += sc[t][1];
            sc[t][2] = __expf(sc[t][2] - m1n); rs1 += sc[t][2];
            sc[t][3] = __expf(sc[t][3] - m1n); rs1 += sc[t][3];
        }
        #pragma unroll
        for (int o = 1; o <= 2; o <<= 1) {
            rs0 += __shfl_xor_sync(0xffffffffu, rs0, o);
            rs1 += __shfl_xor_sync(0xffffffffu, rs1, o);
        }
        l0 = l0 * f0 + rs0;  l1 = l1 * f1 + rs1;
        m0 = m0n;            m1 = m1n;

        #pragma unroll
        for (int d = 0; d < 16; ++d) {
            accO[d][0] *= f0; accO[d][1] *= f0;
            accO[d][2] *= f1; accO[d][3] *= f1;
        }

        // ---- pack P (score C-frag -> A-frag, hi/lo split) ----
        uint32_t ph[4][4], pl[4][4];
        #pragma unroll
        for (int j = 0; j < 4; ++j) {
            pack2(sc[2*j][0],   sc[2*j][1],   ph[j][0], pl[j][0]);
            pack2(sc[2*j][2],   sc[2*j][3],   ph[j][1], pl[j][1]);
            pack2(sc[2*j+1][0], sc[2*j+1][1], ph[j][2], pl[j][2]);
            pack2(sc[2*j+1][2], sc[2*j+1][3], ph[j][3], pl[j][3]);
        }

        // ---- O += P @ V (3-term split) ----
        #pragma unroll
        for (int dp = 0; dp < 8; ++dp) {
            const int ccv = dp * 16 + ((lane >> 4) << 3);
            #pragma unroll
            for (int j = 0; j < 4; ++j) {
                uint32_t r4[4], s4[4];
                const int rv = j * 16 + (lane & 15);
                ldsm4t(r4, s2u(Vh + rv * 136 + ccv));
                ldsm4t(s4, s2u(Vl + rv * 136 + ccv));
                uint32_t bh0[2] = {r4[0], r4[1]}, bh1[2] = {r4[2], r4[3]};
                uint32_t bl0[2] = {s4[0], s4[1]}, bl1[2] = {s4[2], s4[3]};
                mma16816(accO[2*dp],   ph[j], bh0);
                mma16816(accO[2*dp],   ph[j], bl0);
                mma16816(accO[2*dp],   pl[j], bh0);
                mma16816(accO[2*dp+1], ph[j], bh1);
                mma16816(accO[2*dp+1], ph[j], bl1);
                mma16816(accO[2*dp+1], pl[j], bh1);
            }
        }
    }

    // ---- normalize + split-write output ----
    const float i0 = 1.f / l0, i1 = 1.f / l1;
    #pragma unroll
    for (int dt = 0; dt < 16; ++dt) {
        const int col = h * HD + dt * 8 + qd * 2;
        uint32_t hp, lp;
        pack2(accO[dt][0] * i0, accO[dt][1] * i0, hp, lp);
        *(uint32_t*)&ohi[(size_t)row0g * D_MODEL + col] = hp;
        *(uint32_t*)&olo[(size_t)row0g * D_MODEL + col] = lp;
        pack2(accO[dt][2] * i1, accO[dt][3] * i1, hp, lp);
        *(uint32_t*)&ohi[(size_t)row1g * D_MODEL + col] = hp;
        *(uint32_t*)&olo[(size_t)row1g * D_MODEL + col] = lp;
    }
}

// ---------------------------------------------------------------------------
// Launch. Graph-capturable, allocation-free.
// ---------------------------------------------------------------------------
extern "C" void kernel_launch(void* const* d_in, const int* in_sizes, int n_in,
                              void* d_out, int out_size)
{
    const float* x  = (const float*)d_in[0];
    const float* wq = (const float*)d_in[1];
    const float* wk = (const float*)d_in[2];
    const float* wv = (const float*)d_in[3];
    const float* wo = (const float*)d_in[4];
    const float* fc = (const float*)d_in[5];
    const float* fs = (const float*)d_in[6];
    float* out = (float*)d_out;

    __nv_bfloat16 *xhi, *xlo, *wqhi, *wqlo, *wkhi, *wklo, *wvhi, *wvlo, *wohi, *wolo;
    __nv_bfloat16 *qhi, *qlo, *khi, *klo, *vhi, *vlo, *ohi, *olo;
    cudaGetSymbolAddress((void**)&xhi, g_xhi);   cudaGetSymbolAddress((void**)&xlo, g_xlo);
    cudaGetSymbolAddress((void**)&wqhi, g_wqhi); cudaGetSymbolAddress((void**)&wqlo, g_wqlo);
    cudaGetSymbolAddress((void**)&wkhi, g_wkhi); cudaGetSymbolAddress((void**)&wklo, g_wklo);
    cudaGetSymbolAddress((void**)&wvhi, g_wvhi); cudaGetSymbolAddress((void**)&wvlo, g_wvlo);
    cudaGetSymbolAddress((void**)&wohi, g_wohi); cudaGetSymbolAddress((void**)&wolo, g_wolo);
    cudaGetSymbolAddress((void**)&qhi, g_qhi);   cudaGetSymbolAddress((void**)&qlo, g_qlo);
    cudaGetSymbolAddress((void**)&khi, g_khi);   cudaGetSymbolAddress((void**)&klo, g_klo);
    cudaGetSymbolAddress((void**)&vhi, g_vhi);   cudaGetSymbolAddress((void**)&vlo, g_vlo);
    cudaGetSymbolAddress((void**)&ohi, g_ohi);   cudaGetSymbolAddress((void**)&olo, g_olo);

    cudaFuncSetAttribute((const void*)gemm_mma<true,  true >, cudaFuncAttributeMaxDynamicSharedMemorySize, GEMM_SMEM);
    cudaFuncSetAttribute((const void*)gemm_mma<false, true >, cudaFuncAttributeMaxDynamicSharedMemorySize, GEMM_SMEM);
    cudaFuncSetAttribute((const void*)gemm_mma<false, false>, cudaFuncAttributeMaxDynamicSharedMemorySize, GEMM_SMEM);
    cudaFuncSetAttribute((const void*)attn_mma, cudaFuncAttributeMaxDynamicSharedMemorySize, ATTN_SMEM);

    // Input/weight splits
    {
        int n4 = S_LEN * D_MODEL / 4;
        split_k<<<(n4 + 255) / 256, 256>>>(x, xhi, xlo, n4);
        n4 = D_MODEL * D_MODEL / 4;
        split_k<<<(n4 + 255) / 256, 256>>>(wq, wqhi, wqlo, n4);
        split_k<<<(n4 + 255) / 256, 256>>>(wo, wohi, wolo, n4);
        n4 = D_MODEL * KVD / 4;
        split_k<<<(n4 + 255) / 256, 256>>>(wk, wkhi, wklo, n4);
        split_k<<<(n4 + 255) / 256, 256>>>(wv, wvhi, wvlo, n4);
    }

    dim3 blk(256);
    // Q = x @ wq (+RoPE), split output
    gemm_mma<true,  true ><<<dim3(D_MODEL / 128, S_LEN / 128), blk, GEMM_SMEM>>>(
        xhi, xlo, wqhi, wqlo, nullptr, qhi, qlo, S_LEN, D_MODEL, D_MODEL, fc, fs);
    // K = x @ wk (+RoPE), split output
    gemm_mma<true,  true ><<<dim3(KVD / 128, S_LEN / 128), blk, GEMM_SMEM>>>(
        xhi, xlo, wkhi, wklo, nullptr, khi, klo, S_LEN, KVD, D_MODEL, fc, fs);
    // V = x @ wv, split output
    gemm_mma<false, true ><<<dim3(KVD / 128, S_LEN / 128), blk, GEMM_SMEM>>>(
        xhi, xlo, wvhi, wvlo, nullptr, vhi, vlo, S_LEN, KVD, D_MODEL, nullptr, nullptr);
    // Attention (tensorized), split output
    attn_mma<<<dim3(S_LEN / 64, NH), dim3(128), ATTN_SMEM>>>(
        qhi, qlo, khi, klo, vhi, vlo, ohi, olo);
    // out = o @ wo, fp32 output
    gemm_mma<false, false><<<dim3(D_MODEL / 128, S_LEN / 128), blk, GEMM_SMEM>>>(
        ohi, olo, wohi, wolo, out, nullptr, nullptr, S_LEN, D_MODEL, D_MODEL, nullptr, nullptr);
}